// round 4
// baseline (speedup 1.0000x reference)
#include <cuda_runtime.h>
#include <cstdint>

#define B_ROWS 2000000u
#define F_COLS 21u
#define N_ELEM (B_ROWS * F_COLS)          // 42,000,000
#define N_VEC  (N_ELEM / 4u)              // 10,500,000
#define NUM_CLASSES 7

// stride_elems = NBLOCKS*256*4 must be ≡ 0 (mod 21) -> NBLOCKS ≡ 0 (mod 21).
// 735 = 21*35 and 735 <= 148 SMs * 5 blocks/SM (740) => exactly one wave.
#define NBLOCKS 735
#define NTHREADS 256
#define STRIDE_VEC (NBLOCKS * NTHREADS)   // 188,160 vec4s; *4 = 752,640 ≡ 0 (mod 21)

__device__ double        g_part_wd[NBLOCKS];
__device__ double        g_part_pen[NBLOCKS];
__device__ unsigned int  g_done_count = 0;

__device__ __forceinline__ void proc_vec4(
    const float4 xv, const int4 tv, unsigned v, unsigned c,
    bool boundary, unsigned s, int kp,
    const int* __restrict__ t, const float* sw,
    float& accw, float& accp)
{
    const unsigned cbase = v * 4u - c;            // element index of row start
    const int   cls0 = __ldg(t + cbase + 2u);     // same line as the int4 stream -> L1 hit
    const float w0   = sw[(unsigned)cls0 / 100u - 1u];

    const float d0 = xv.x - (float)tv.x;
    const float d1 = xv.y - (float)tv.y;
    const float d2 = xv.z - (float)tv.z;
    const float d3 = xv.w - (float)tv.w;
    const float q0 = d0 * d0, q1 = d1 * d1, q2 = d2 * d2, q3 = d3 * d3;
    const float q  = (q0 + q1) + (q2 + q3);
    accw = fmaf(w0, q, accw);

    if (boundary) {                               // loop-invariant predicate
        const int   cls1 = __ldg(t + cbase + 23u);
        const float w1   = sw[(unsigned)cls1 / 100u - 1u];
        float qhi = q3;                           // lanes k >= s belong to next row
        if (s <= 2u) qhi += q2;
        if (s <= 1u) qhi += q1;
        accw = fmaf(w1 - w0, qhi, accw);
    }
    if (kp >= 0) {                                // loop-invariant predicate
        const int tp = (kp == 0) ? tv.x : (kp == 1) ? tv.y : (kp == 2) ? tv.z : tv.w;
        const float vv = (float)tp;
        if (vv > 1000.0f) {
            const float e = vv - 1000.0f;
            accp = fmaf(e, e, accp);
        } else if (vv < 0.0f) {
            accp = fmaf(vv, vv, accp);
        }
    }
}

__global__ __launch_bounds__(NTHREADS, 5)
void wmse_fused_kernel(const float* __restrict__ x,
                       const int*   __restrict__ t,
                       const float* __restrict__ w,
                       float*       __restrict__ out)
{
    __shared__ float sw[NUM_CLASSES];
    __shared__ float s_wd[NTHREADS / 32];
    __shared__ float s_pen[NTHREADS / 32];
    __shared__ bool  s_is_last;

    if (threadIdx.x < NUM_CLASSES) sw[threadIdx.x] = w[threadIdx.x];
    __syncthreads();

    const unsigned v0   = blockIdx.x * NTHREADS + threadIdx.x;
    const unsigned base = v0 * 4u;
    const unsigned r0   = base / F_COLS;            // magic-mul once
    const unsigned c    = base - r0 * F_COLS;       // loop-invariant column phase

    const bool     boundary = (c >= 18u);
    const unsigned s        = F_COLS - c;           // first k of next row (1..3 if boundary)
    int kp = -1;                                    // penalty lane (col==1), at most one
    if      (c <= 1u)  kp = 1 - (int)c;             // ck == 1
    else if (c >= 19u) kp = 22 - (int)c;            // ck == 22 (next row, col 1)

    float accw0 = 0.0f, accw1 = 0.0f, accp = 0.0f;

    const float4* __restrict__ xv4 = reinterpret_cast<const float4*>(x);
    const int4*   __restrict__ tv4 = reinterpret_cast<const int4*>(t);

    unsigned v = v0;
    // unroll x4, all 8 big loads front-batched for max MLP
    for (; v + 3u * STRIDE_VEC < N_VEC; v += 4u * STRIDE_VEC) {
        const unsigned va = v;
        const unsigned vb = v +      STRIDE_VEC;
        const unsigned vc = v + 2u * STRIDE_VEC;
        const unsigned vd = v + 3u * STRIDE_VEC;

        const float4 xa = __ldg(xv4 + va);
        const int4   ta = __ldg(tv4 + va);
        const float4 xb = __ldg(xv4 + vb);
        const int4   tb = __ldg(tv4 + vb);
        const float4 xc = __ldg(xv4 + vc);
        const int4   tc = __ldg(tv4 + vc);
        const float4 xd = __ldg(xv4 + vd);
        const int4   td = __ldg(tv4 + vd);

        proc_vec4(xa, ta, va, c, boundary, s, kp, t, sw, accw0, accp);
        proc_vec4(xb, tb, vb, c, boundary, s, kp, t, sw, accw1, accp);
        proc_vec4(xc, tc, vc, c, boundary, s, kp, t, sw, accw0, accp);
        proc_vec4(xd, td, vd, c, boundary, s, kp, t, sw, accw1, accp);
    }
    for (; v < N_VEC; v += STRIDE_VEC) {
        const float4 xa = __ldg(xv4 + v);
        const int4   ta = __ldg(tv4 + v);
        proc_vec4(xa, ta, v, c, boundary, s, kp, t, sw, accw0, accp);
    }

    float accw = accw0 + accw1;

    // warp reduce
    #pragma unroll
    for (int o = 16; o > 0; o >>= 1) {
        accw += __shfl_xor_sync(0xffffffffu, accw, o);
        accp += __shfl_xor_sync(0xffffffffu, accp, o);
    }
    const int warp = threadIdx.x >> 5;
    const int lane = threadIdx.x & 31;
    if (lane == 0) { s_wd[warp] = accw; s_pen[warp] = accp; }
    __syncthreads();

    if (threadIdx.x == 0) {
        double dw = 0.0, dp = 0.0;
        #pragma unroll
        for (int i = 0; i < NTHREADS / 32; ++i) { dw += (double)s_wd[i]; dp += (double)s_pen[i]; }
        g_part_wd[blockIdx.x]  = dw;
        g_part_pen[blockIdx.x] = dp;
        __threadfence();
        const unsigned prev = atomicAdd(&g_done_count, 1u);
        s_is_last = (prev == (unsigned)(gridDim.x - 1));
    }
    __syncthreads();

    if (s_is_last) {
        __threadfence();
        double dw = 0.0, dp = 0.0;
        for (int i = threadIdx.x; i < NBLOCKS; i += NTHREADS) {
            dw += g_part_wd[i];
            dp += g_part_pen[i];
        }
        #pragma unroll
        for (int o = 16; o > 0; o >>= 1) {
            dw += __shfl_xor_sync(0xffffffffu, dw, o);
            dp += __shfl_xor_sync(0xffffffffu, dp, o);
        }
        __shared__ double f_wd[NTHREADS / 32];
        __shared__ double f_pen[NTHREADS / 32];
        if (lane == 0) { f_wd[warp] = dw; f_pen[warp] = dp; }
        __syncthreads();
        if (threadIdx.x == 0) {
            double tw = 0.0, tp = 0.0;
            #pragma unroll
            for (int i = 0; i < NTHREADS / 32; ++i) { tw += f_wd[i]; tp += f_pen[i]; }
            const double mean_wd = tw / (double)((unsigned long long)B_ROWS * F_COLS);
            out[0] = (float)(mean_wd + tp);
            g_done_count = 0;   // reset for next graph replay
        }
    }
}

extern "C" void kernel_launch(void* const* d_in, const int* in_sizes, int n_in,
                              void* d_out, int out_size)
{
    const float* x = nullptr;
    const int*   t = nullptr;
    const float* w = nullptr;
    int big_seen = 0;
    for (int i = 0; i < n_in; ++i) {
        if (in_sizes[i] == NUM_CLASSES) {
            w = (const float*)d_in[i];
        } else {
            if (big_seen == 0) x = (const float*)d_in[i];
            else               t = (const int*)d_in[i];
            big_seen++;
        }
    }
    wmse_fused_kernel<<<NBLOCKS, NTHREADS>>>(x, t, w, (float*)d_out);
}

// round 6
// speedup vs baseline: 1.0271x; 1.0271x over previous
#include <cuda_runtime.h>
#include <cstdint>

#define B_ROWS   2000000u
#define F_COLS   21u
#define NUM_CLASSES 7

#define NBLOCKS  740              // = 148 SMs * 5 blocks: exactly one perfectly balanced wave
#define NTHREADS 256

// Rows are handed out in quads (4 rows = 84 elems = 336 B, keeps every tile 16B-aligned).
#define TOTAL_QUADS 500000u       // 2,000,000 / 4
#define QUADS_LO    675u          // 740*675 + 500 = 500000
#define BIG_BLOCKS  500u          // first 500 blocks get 676 quads

#define TILE_ROWS  64u
#define TILE_ELEMS (TILE_ROWS * F_COLS)   // 1344
#define TILE_VEC   (TILE_ELEMS / 4u)      // 336
#define TILE_BYTES (TILE_ELEMS * 4u)      // 5376 per array
#define DEPTH      4

__device__ double        g_part_wd[NBLOCKS];
__device__ double        g_part_pen[NBLOCKS];
__device__ unsigned int  g_done_count = 0;

// ---------- PTX helpers ----------
__device__ __forceinline__ unsigned smem_u32(const void* p) {
    return (unsigned)__cvta_generic_to_shared(p);
}
__device__ __forceinline__ void mbar_init(unsigned a, unsigned cnt) {
    asm volatile("mbarrier.init.shared.b64 [%0], %1;" :: "r"(a), "r"(cnt) : "memory");
}
__device__ __forceinline__ void mbar_expect_tx(unsigned a, unsigned bytes) {
    asm volatile("mbarrier.arrive.expect_tx.shared.b64 _, [%0], %1;"
                 :: "r"(a), "r"(bytes) : "memory");
}
__device__ __forceinline__ void bulk_g2s(unsigned dst, const void* src, unsigned bytes, unsigned mbar) {
    asm volatile("cp.async.bulk.shared::cluster.global.mbarrier::complete_tx::bytes [%0], [%1], %2, [%3];"
                 :: "r"(dst), "l"(src), "r"(bytes), "r"(mbar) : "memory");
}
__device__ __forceinline__ void mbar_wait(unsigned a, unsigned parity) {
    asm volatile(
        "{\n\t"
        ".reg .pred P;\n"
        "W%=:\n\t"
        "mbarrier.try_wait.parity.acquire.cta.shared::cta.b64 P, [%0], %1, 0x989680;\n\t"
        "@P bra D%=;\n\t"
        "bra W%=;\n"
        "D%=:\n\t"
        "}" :: "r"(a), "r"(parity) : "memory");
}

__global__ __launch_bounds__(NTHREADS, 5)
void wmse_tma_kernel(const float* __restrict__ x,
                     const int*   __restrict__ t,
                     const float* __restrict__ w,
                     float*       __restrict__ out)
{
    __shared__ alignas(128) float s_x[DEPTH][TILE_ELEMS];
    __shared__ alignas(128) int   s_t[DEPTH][TILE_ELEMS];
    __shared__ alignas(16)  unsigned long long s_mbar[DEPTH];
    __shared__ float  s_wrow[TILE_ROWS];
    __shared__ float  s_wtab[NUM_CLASSES];
    __shared__ float  s_rwd[NTHREADS / 32];
    __shared__ float  s_rpen[NTHREADS / 32];
    __shared__ bool   s_is_last;

    const unsigned tid = threadIdx.x;
    const unsigned b   = blockIdx.x;

    // Block's row range (in quads so every tile start is 16B-aligned).
    const unsigned nquads    = (b < BIG_BLOCKS) ? (QUADS_LO + 1u) : QUADS_LO;
    const unsigned startq    = QUADS_LO * b + min(b, BIG_BLOCKS);
    const unsigned rows      = nquads * 4u;
    const unsigned elem_base = startq * 84u;                 // 84 elems per quad
    const unsigned ntiles    = (rows + TILE_ROWS - 1u) / TILE_ROWS;   // 43 for all blocks

    if (tid < NUM_CLASSES) s_wtab[tid] = w[tid];
    if (tid == 0) {
        #pragma unroll
        for (int sidx = 0; sidx < DEPTH; ++sidx)
            mbar_init(smem_u32(&s_mbar[sidx]), 1u);
    }
    __syncthreads();

    // Prime the pipeline
    if (tid == 0) {
        #pragma unroll
        for (unsigned i = 0; i < DEPTH; ++i) {
            const unsigned trows = min(TILE_ROWS, rows - i * TILE_ROWS);
            const unsigned bytes = trows * F_COLS * 4u;
            const unsigned mb    = smem_u32(&s_mbar[i]);
            mbar_expect_tx(mb, 2u * bytes);
            bulk_g2s(smem_u32(&s_x[i][0]), x + elem_base + i * TILE_ELEMS, bytes, mb);
            bulk_g2s(smem_u32(&s_t[i][0]), t + elem_base + i * TILE_ELEMS, bytes, mb);
        }
    }

    // Per-thread slot constants (tile length ≡ 0 mod 21 -> phases fixed across tiles)
    const unsigned j0 = tid;
    const unsigned j1 = tid + NTHREADS;          // valid only when j1 < nvec (tid < 80 full tiles)
    const unsigned e0 = j0 * 4u,  e1 = j1 * 4u;
    const unsigned r0 = e0 / F_COLS, r1 = e1 / F_COLS;
    const unsigned c0 = e0 - r0 * F_COLS, c1 = e1 - r1 * F_COLS;
    const bool     bd0 = (c0 >= 18u),  bd1 = (c1 >= 18u);
    const unsigned sp0 = F_COLS - c0,  sp1 = F_COLS - c1;

    float accw = 0.0f, accp = 0.0f;

    for (unsigned i = 0; i < ntiles; ++i) {
        const unsigned stg = i & (DEPTH - 1u);
        mbar_wait(smem_u32(&s_mbar[stg]), (i / DEPTH) & 1u);

        const unsigned trows = min(TILE_ROWS, rows - i * TILE_ROWS);
        // Per-row work: weight table + penalty (each row exactly once, from smem)
        if (tid < trows) {
            const int cls = s_t[stg][tid * F_COLS + 2u];
            s_wrow[tid] = s_wtab[(unsigned)cls / 100u - 1u];
            const float vv = (float)s_t[stg][tid * F_COLS + 1u];
            if (vv > 1000.0f) {
                const float e = vv - 1000.0f;
                accp = fmaf(e, e, accp);
            } else if (vv < 0.0f) {
                accp = fmaf(vv, vv, accp);
            }
        }
        __syncthreads();

        const unsigned nvec = trows * F_COLS / 4u;   // trows mult of 4 -> exact

        if (j0 < nvec) {
            const float4 xv = *reinterpret_cast<const float4*>(&s_x[stg][e0]);
            const int4   tv = *reinterpret_cast<const int4*>(&s_t[stg][e0]);
            const float w0 = s_wrow[r0];
            const float d0 = xv.x - (float)tv.x;
            const float d1 = xv.y - (float)tv.y;
            const float d2 = xv.z - (float)tv.z;
            const float d3 = xv.w - (float)tv.w;
            const float q0 = d0*d0, q1 = d1*d1, q2 = d2*d2, q3 = d3*d3;
            const float q  = (q0 + q1) + (q2 + q3);
            accw = fmaf(w0, q, accw);
            if (bd0) {
                const float w1 = s_wrow[r0 + 1u];
                float qhi = q3;
                if (sp0 <= 2u) qhi += q2;
                if (sp0 <= 1u) qhi += q1;
                accw = fmaf(w1 - w0, qhi, accw);
            }
        }
        if (j1 < nvec) {
            const float4 xv = *reinterpret_cast<const float4*>(&s_x[stg][e1]);
            const int4   tv = *reinterpret_cast<const int4*>(&s_t[stg][e1]);
            const float w0 = s_wrow[r1];
            const float d0 = xv.x - (float)tv.x;
            const float d1 = xv.y - (float)tv.y;
            const float d2 = xv.z - (float)tv.z;
            const float d3 = xv.w - (float)tv.w;
            const float q0 = d0*d0, q1 = d1*d1, q2 = d2*d2, q3 = d3*d3;
            const float q  = (q0 + q1) + (q2 + q3);
            accw = fmaf(w0, q, accw);
            if (bd1) {
                const float w1 = s_wrow[r1 + 1u];
                float qhi = q3;
                if (sp1 <= 2u) qhi += q2;
                if (sp1 <= 1u) qhi += q1;
                accw = fmaf(w1 - w0, qhi, accw);
            }
        }
        __syncthreads();   // stage + w_row fully consumed

        // Refill this stage with tile i+DEPTH
        const unsigned nx = i + DEPTH;
        if (tid == 0 && nx < ntiles) {
            const unsigned trN   = min(TILE_ROWS, rows - nx * TILE_ROWS);
            const unsigned bytes = trN * F_COLS * 4u;
            const unsigned mb    = smem_u32(&s_mbar[stg]);
            mbar_expect_tx(mb, 2u * bytes);
            bulk_g2s(smem_u32(&s_x[stg][0]), x + elem_base + nx * TILE_ELEMS, bytes, mb);
            bulk_g2s(smem_u32(&s_t[stg][0]), t + elem_base + nx * TILE_ELEMS, bytes, mb);
        }
    }

    // ---- block reduction ----
    #pragma unroll
    for (int o = 16; o > 0; o >>= 1) {
        accw += __shfl_xor_sync(0xffffffffu, accw, o);
        accp += __shfl_xor_sync(0xffffffffu, accp, o);
    }
    const int warp = tid >> 5;
    const int lane = tid & 31;
    if (lane == 0) { s_rwd[warp] = accw; s_rpen[warp] = accp; }
    __syncthreads();

    if (tid == 0) {
        double dw = 0.0, dp = 0.0;
        #pragma unroll
        for (int i = 0; i < NTHREADS / 32; ++i) { dw += (double)s_rwd[i]; dp += (double)s_rpen[i]; }
        g_part_wd[b]  = dw;
        g_part_pen[b] = dp;
        __threadfence();
        const unsigned prev = atomicAdd(&g_done_count, 1u);
        s_is_last = (prev == (unsigned)(gridDim.x - 1));
    }
    __syncthreads();

    if (s_is_last) {
        __threadfence();
        double dw = 0.0, dp = 0.0;
        for (unsigned i = tid; i < NBLOCKS; i += NTHREADS) {
            dw += g_part_wd[i];
            dp += g_part_pen[i];
        }
        #pragma unroll
        for (int o = 16; o > 0; o >>= 1) {
            dw += __shfl_xor_sync(0xffffffffu, dw, o);
            dp += __shfl_xor_sync(0xffffffffu, dp, o);
        }
        __shared__ double f_wd[NTHREADS / 32];
        __shared__ double f_pen[NTHREADS / 32];
        if (lane == 0) { f_wd[warp] = dw; f_pen[warp] = dp; }
        __syncthreads();
        if (tid == 0) {
            double tw = 0.0, tp = 0.0;
            #pragma unroll
            for (int i = 0; i < NTHREADS / 32; ++i) { tw += f_wd[i]; tp += f_pen[i]; }
            const double mean_wd = tw / (double)((unsigned long long)B_ROWS * F_COLS);
            out[0] = (float)(mean_wd + tp);
            g_done_count = 0;   // reset for next graph replay
        }
    }
}

extern "C" void kernel_launch(void* const* d_in, const int* in_sizes, int n_in,
                              void* d_out, int out_size)
{
    const float* x = nullptr;
    const int*   t = nullptr;
    const float* w = nullptr;
    int big_seen = 0;
    for (int i = 0; i < n_in; ++i) {
        if (in_sizes[i] == NUM_CLASSES) {
            w = (const float*)d_in[i];
        } else {
            if (big_seen == 0) x = (const float*)d_in[i];
            else               t = (const int*)d_in[i];
            big_seen++;
        }
    }
    wmse_tma_kernel<<<NBLOCKS, NTHREADS>>>(x, t, w, (float*)d_out);
}